// round 5
// baseline (speedup 1.0000x reference)
#include <cuda_runtime.h>
#include <cstdint>

#define DD 256
#define NTOK 16384
#define KCB 8192
#define BM 128
#define BN 128
#define NNT (KCB/BN)     // 64
#define NDC 8            // D chunks of 32
#define NIT (NNT*NDC)    // 512
#define LDT 36           // padded smem row (floats)
#define OPB (BM*LDT*4)   // 18432 B per operand tile
#define STGB (2*OPB)     // 36864 B per stage (A hi + B hi)
#define SBD  (4*STGB)            // s_m1
#define SB2  (SBD + 8192)        // s_m2
#define SII  (SBD + 16384)       // s_i1
#define SIDX (SBD + 24576)       // s_idx
#define SMEMSZ (SBD + 24576 + 512)
#define FLAG_T 0.12f
#define FLAG_CAP 4096

__device__ __align__(128) float g_xhi[NTOK*DD];
__device__ __align__(128) float g_ehi[KCB*DD];
__device__ __align__(128) float g_esq[KCB];
__device__ int g_flag[FLAG_CAP];
__device__ int g_cnt;

#define CP16(d,s)   asm volatile("cp.async.cg.shared.global [%0], [%1], 16;"::"r"(d),"l"(s):"memory")
#define CP_COMMIT() asm volatile("cp.async.commit_group;":::"memory")
#define CP_WAIT(n)  asm volatile("cp.async.wait_group %0;"::"n"(n):"memory")

__device__ __forceinline__ uint32_t s2u(const void* p){
    uint32_t a; asm("{ .reg .u64 t; cvta.to.shared.u64 t, %1; cvt.u32.u64 %0, t; }":"=r"(a):"l"(p)); return a;
}
__device__ __forceinline__ void mma8(float* d, const uint32_t* a, const uint32_t* b){
    asm("mma.sync.aligned.m16n8k8.row.col.f32.tf32.tf32.f32 "
        "{%0,%1,%2,%3}, {%4,%5,%6,%7}, {%8,%9}, {%0,%1,%2,%3};"
        : "+f"(d[0]),"+f"(d[1]),"+f"(d[2]),"+f"(d[3])
        : "r"(a[0]),"r"(a[1]),"r"(a[2]),"r"(a[3]),"r"(b[0]),"r"(b[1]));
}
__device__ __forceinline__ float tf32r(float x){
    uint32_t b; asm("cvt.rna.tf32.f32 %0, %1;":"=r"(b):"f"(x)); return __uint_as_float(b);
}

// ---- prep ----
__global__ void split_kernel(const float4* __restrict__ s, float4* __restrict__ h, int n4){
    int i = blockIdx.x*blockDim.x + threadIdx.x; if(i>=n4) return;
    float4 v=s[i], a;
    a.x=tf32r(v.x); a.y=tf32r(v.y); a.z=tf32r(v.z); a.w=tf32r(v.w);
    h[i]=a;
}
__global__ void sumsq_kernel(const float* __restrict__ x, float* __restrict__ o, int rows){
    if(blockIdx.x==0 && threadIdx.x==0) g_cnt = 0;
    int row = blockIdx.x*(blockDim.x>>5) + (threadIdx.x>>5); if(row>=rows) return;
    int lane = threadIdx.x&31; const float* p = x + (size_t)row*DD; float s=0.f;
    #pragma unroll
    for(int c=lane;c<DD;c+=32){ float v=p[c]; s+=v*v; }
    #pragma unroll
    for(int ofs=16;ofs;ofs>>=1) s+=__shfl_down_sync(0xffffffffu,s,ofs);
    if(!lane) o[row]=s;
}

__device__ __forceinline__ void issue_stage(uint32_t sb, int it, int m0, int tid,
        const float* __restrict__ xhi, const float* __restrict__ ehi){
    const int nt = it>>3, dc = it&7;
    const uint32_t tb = sb + (uint32_t)(it&3)*STGB;
    #pragma unroll
    for(int i=0;i<8;i++){
        int idx = tid + i*256;
        int op = idx>>10, rem = idx&1023, row = rem>>3, c4 = rem&7;
        uint32_t dst = tb + op*OPB + row*(LDT*4) + c4*16;
        const float* src = (op ? ehi + (size_t)(nt*BN+row)*DD
                               : xhi + (size_t)(m0+row)*DD) + dc*32 + c4*4;
        CP16(dst, src);
    }
    CP_COMMIT();
}

// ---- phase 1: approx GEMM + min1/min2 tracking ----
__global__ void __launch_bounds__(256,1) vq_phase1(
    const float* __restrict__ xhi, const float* __restrict__ ehi,
    const float* __restrict__ E,   const float* __restrict__ esq,
    float* __restrict__ outq, float* __restrict__ outi)
{
    extern __shared__ char smem[];
    const uint32_t sb = s2u(smem);
    const int tid = threadIdx.x, wid = tid>>5, lane = tid&31;
    const int r = lane>>2, c = lane&3;
    const int wm = wid&1, wn = wid>>1;
    const int m0 = blockIdx.x*BM;

    float m1[8], m2[8]; int i1[8];
    #pragma unroll
    for(int i=0;i<8;i++){ m1[i]=3.4e38f; m2[i]=3.4e38f; i1[i]=0; }

    issue_stage(sb,0,m0,tid,xhi,ehi);
    issue_stage(sb,1,m0,tid,xhi,ehi);
    issue_stage(sb,2,m0,tid,xhi,ehi);

    for(int nt=0; nt<NNT; nt++){
        float acc[4][4][4];
        #pragma unroll
        for(int m=0;m<4;m++)
            #pragma unroll
            for(int n=0;n<4;n++){ acc[m][n][0]=0.f;acc[m][n][1]=0.f;acc[m][n][2]=0.f;acc[m][n][3]=0.f; }

        for(int dc=0; dc<NDC; dc++){
            const int it = nt*NDC + dc;
            if(it < NIT-2)      { CP_WAIT(2); }
            else if(it == NIT-2){ CP_WAIT(1); }
            else                { CP_WAIT(0); }
            __syncthreads();
            if(it+3 < NIT) issue_stage(sb, it+3, m0, tid, xhi, ehi);
            const char* stp = smem + (size_t)(it&3)*STGB;

            #pragma unroll
            for(int ks=0; ks<4; ks++){
                uint32_t ah[4][4], bh[4][2];
                #pragma unroll
                for(int m=0;m<4;m++){
                    int off = ((wm*64 + m*16 + r)*LDT + ks*8 + c)*4;
                    ah[m][0]=*(const uint32_t*)(stp+off);
                    ah[m][1]=*(const uint32_t*)(stp+off+8*LDT*4);
                    ah[m][2]=*(const uint32_t*)(stp+off+16);
                    ah[m][3]=*(const uint32_t*)(stp+off+8*LDT*4+16);
                }
                #pragma unroll
                for(int n=0;n<4;n++){
                    int off = OPB + ((wn*32 + n*8 + r)*LDT + ks*8 + c)*4;
                    bh[n][0]=*(const uint32_t*)(stp+off);
                    bh[n][1]=*(const uint32_t*)(stp+off+16);
                }
                #pragma unroll
                for(int m=0;m<4;m++)
                    #pragma unroll
                    for(int n=0;n<4;n++) mma8(acc[m][n], ah[m], bh[n]);
            }
        }
        // fold with min1/min2 tracking (cols ascending per slot)
        #pragma unroll
        for(int m=0;m<4;m++){
            const int rl=2*m, rh=2*m+1;
            #pragma unroll
            for(int n=0;n<4;n++){
                int colb = nt*BN + wn*32 + n*8 + 2*c;
                float e0 = __ldg(esq+colb), e1 = __ldg(esq+colb+1);
                float d;
                d = e0 - 2.f*acc[m][n][0];
                if(d<m1[rl]){m2[rl]=m1[rl];m1[rl]=d;i1[rl]=colb;} else if(d<m2[rl]) m2[rl]=d;
                d = e1 - 2.f*acc[m][n][1];
                if(d<m1[rl]){m2[rl]=m1[rl];m1[rl]=d;i1[rl]=colb+1;} else if(d<m2[rl]) m2[rl]=d;
                d = e0 - 2.f*acc[m][n][2];
                if(d<m1[rh]){m2[rh]=m1[rh];m1[rh]=d;i1[rh]=colb;} else if(d<m2[rh]) m2[rh]=d;
                d = e1 - 2.f*acc[m][n][3];
                if(d<m1[rh]){m2[rh]=m1[rh];m1[rh]=d;i1[rh]=colb+1;} else if(d<m2[rh]) m2[rh]=d;
            }
        }
    }

    float* s_m1 = (float*)(smem + SBD);
    float* s_m2 = (float*)(smem + SB2);
    int*   s_i1 = (int*)(smem + SII);
    int*   s_idx= (int*)(smem + SIDX);
    __syncthreads();
    #pragma unroll
    for(int i=0;i<8;i++){
        int row  = wm*64 + (i>>1)*16 + r + (i&1)*8;
        int slot = wn*4 + c;
        s_m1[row*16+slot] = m1[i];
        s_m2[row*16+slot] = m2[i];
        s_i1[row*16+slot] = i1[i];
    }
    __syncthreads();
    if(tid < 128){
        float bd = 3.4e38f; int bi = 0, tw = 0;
        #pragma unroll
        for(int t=0;t<16;t++){
            float d = s_m1[tid*16+t]; int ii = s_i1[tid*16+t];
            if(d<bd || (d==bd && ii<bi)){ bd=d; bi=ii; tw=t; }
        }
        float b2 = 3.4e38f;
        #pragma unroll
        for(int t=0;t<16;t++){
            float v = (t==tw) ? s_m2[tid*16+t] : s_m1[tid*16+t];
            b2 = fminf(b2, v);
        }
        s_idx[tid] = bi;
        outi[m0+tid] = (float)bi;
        if(b2 - bd < FLAG_T){
            int pos = atomicAdd(&g_cnt, 1);
            if(pos < FLAG_CAP) g_flag[pos] = m0 + tid;
        }
    }
    __syncthreads();
    for(int f=tid; f<BM*(DD/4); f+=256){
        int rr = f>>6, c4 = f&63;
        float4 v = *(const float4*)(E + (size_t)s_idx[rr]*DD + c4*4);
        *(float4*)(outq + (size_t)(m0+rr)*DD + c4*4) = v;
    }
}

// ---- phase 2: exact fp32 rescore of flagged rows (warp per row) ----
__global__ void __launch_bounds__(256) vq_phase2(
    const float* __restrict__ X, const float* __restrict__ E,
    const float* __restrict__ esq, float* __restrict__ outq, float* __restrict__ outi)
{
    const int wid = threadIdx.x>>5, lane = threadIdx.x&31;
    const int i = blockIdx.x*8 + wid;
    if(i >= g_cnt) return;
    const int row = g_flag[i];
    const int g = lane>>3, l8 = lane&7;

    // x distributed: lane holds x[k*32 + l8*4 .. +3] for k=0..7
    float4 xr[8];
    #pragma unroll
    for(int k=0;k<8;k++) xr[k] = *(const float4*)(X + (size_t)row*DD + k*32 + l8*4);

    float bd = 3.4e38f; int bi = 0;
    for(int j0=0; j0<KCB; j0+=8){
        int ja = j0 + g, jb = j0 + 4 + g;
        const float* ea = E + (size_t)ja*DD;
        const float* eb = E + (size_t)jb*DD;
        float da = 0.f, db = 0.f;
        #pragma unroll
        for(int k=0;k<8;k++){
            float4 u = *(const float4*)(ea + k*32 + l8*4);
            float4 v = *(const float4*)(eb + k*32 + l8*4);
            da += xr[k].x*u.x + xr[k].y*u.y + xr[k].z*u.z + xr[k].w*u.w;
            db += xr[k].x*v.x + xr[k].y*v.y + xr[k].z*v.z + xr[k].w*v.w;
        }
        #pragma unroll
        for(int o=1;o<8;o<<=1){
            da += __shfl_xor_sync(0xffffffffu, da, o);
            db += __shfl_xor_sync(0xffffffffu, db, o);
        }
        float d;
        d = __ldg(esq+ja) - 2.f*da; if(d<bd){ bd=d; bi=ja; }
        d = __ldg(esq+jb) - 2.f*db; if(d<bd){ bd=d; bi=jb; }
    }
    // cross-group (codes interleaved mod 4): idx tiebreak keeps first occurrence
    #pragma unroll
    for(int o=8;o<=16;o<<=1){
        float od = __shfl_xor_sync(0xffffffffu, bd, o);
        int   oi = __shfl_xor_sync(0xffffffffu, bi, o);
        if(od<bd || (od==bd && oi<bi)){ bd=od; bi=oi; }
    }
    if(lane==0) outi[row] = (float)bi;
    float4 v0 = *(const float4*)(E + (size_t)bi*DD + lane*8);
    float4 v1 = *(const float4*)(E + (size_t)bi*DD + lane*8 + 4);
    *(float4*)(outq + (size_t)row*DD + lane*8)     = v0;
    *(float4*)(outq + (size_t)row*DD + lane*8 + 4) = v1;
}

extern "C" void kernel_launch(void* const* d_in, const int* in_sizes, int n_in,
                              void* d_out, int out_size) {
    const float* X = (const float*)d_in[0];
    const float* E = (const float*)d_in[1];

    float *xhi,*ehi,*esq;
    cudaGetSymbolAddress((void**)&xhi, g_xhi);
    cudaGetSymbolAddress((void**)&ehi, g_ehi);
    cudaGetSymbolAddress((void**)&esq, g_esq);

    split_kernel<<<NTOK*DD/4/256, 256>>>((const float4*)X, (float4*)xhi, NTOK*DD/4);
    split_kernel<<<KCB*DD/4/256, 256>>>((const float4*)E, (float4*)ehi, KCB*DD/4);
    sumsq_kernel<<<KCB/8, 256>>>(E, esq, KCB);   // also zeroes g_cnt

    float* outq = (float*)d_out;
    float* outi = (float*)d_out + (size_t)NTOK*DD;

    cudaFuncSetAttribute(vq_phase1, cudaFuncAttributeMaxDynamicSharedMemorySize, SMEMSZ);
    vq_phase1<<<NTOK/BM, 256, SMEMSZ>>>(xhi, ehi, E, esq, outq, outi);
    vq_phase2<<<FLAG_CAP/8, 256>>>(X, E, esq, outq, outi);
}

// round 6
// speedup vs baseline: 2.5537x; 2.5537x over previous
#include <cuda_runtime.h>
#include <cstdint>

#define DD 256
#define NTOK 16384
#define KCB 8192
#define BM 128
#define BN 128
#define NNT (KCB/BN)
#define NIT (NNT*8)
#define STGB 32768
#define SBD  (4*STGB)
#define SB2  (SBD + 8192)
#define SII  (SBD + 16384)
#define SIDX (SBD + 24576)
#define SMEMSZ (SBD + 25088)
#define FLAG_T 0.12f
#define FLAG_CAP 4096
#define P2M 64

__device__ __align__(128) float4 g_xp[NTOK/16*32*32];
__device__ __align__(128) float2 g_ep[KCB/8*32*32];
__device__ __align__(128) float g_esq[KCB];
__device__ unsigned long long g_best[NTOK];
__device__ int g_flag[FLAG_CAP];
__device__ int g_cnt;

#define CP16(d,s)   asm volatile("cp.async.cg.shared.global [%0], [%1], 16;"::"r"(d),"l"(s):"memory")
#define CP_COMMIT() asm volatile("cp.async.commit_group;":::"memory")
#define CP_WAIT(n)  asm volatile("cp.async.wait_group %0;"::"n"(n):"memory")

__device__ __forceinline__ uint32_t s2u(const void* p){
    uint32_t a; asm("{ .reg .u64 t; cvta.to.shared.u64 t, %1; cvt.u32.u64 %0, t; }":"=r"(a):"l"(p)); return a;
}
__device__ __forceinline__ void mma8(float* d, const uint32_t* a, const uint32_t* b){
    asm("mma.sync.aligned.m16n8k8.row.col.f32.tf32.tf32.f32 "
        "{%0,%1,%2,%3}, {%4,%5,%6,%7}, {%8,%9}, {%0,%1,%2,%3};"
        : "+f"(d[0]),"+f"(d[1]),"+f"(d[2]),"+f"(d[3])
        : "r"(a[0]),"r"(a[1]),"r"(a[2]),"r"(a[3]),"r"(b[0]),"r"(b[1]));
}
__device__ __forceinline__ float tf32r(float x){
    uint32_t b; asm("cvt.rna.tf32.f32 %0, %1;":"=r"(b):"f"(x)); return __uint_as_float(b);
}

// ---- prep: pack A fragments (per 16x8 tile, lane-major float4) ----
__global__ void packA(const float* __restrict__ src, float4* __restrict__ dst){
    int i = blockIdx.x*blockDim.x + threadIdx.x;      // NTOK/16*32*32 total
    int lane = i&31, kc = (i>>5)&31, t = i>>10;
    int gr = lane>>2, gc = lane&3;
    int r0 = t*16+gr, c0 = kc*8+gc;
    float4 v;
    v.x = tf32r(src[(size_t)r0*DD + c0]);
    v.y = tf32r(src[(size_t)(r0+8)*DD + c0]);
    v.z = tf32r(src[(size_t)r0*DD + c0+4]);
    v.w = tf32r(src[(size_t)(r0+8)*DD + c0+4]);
    dst[i] = v;
}
// ---- prep: pack B fragments (per 8x8 tile, lane-major float2) ----
__global__ void packB(const float* __restrict__ src, float2* __restrict__ dst){
    int i = blockIdx.x*blockDim.x + threadIdx.x;      // KCB/8*32*32 total
    int lane = i&31, kc = (i>>5)&31, n8 = i>>10;
    int gr = lane>>2, gc = lane&3;
    int r = n8*8+gr, c0 = kc*8+gc;
    float2 v;
    v.x = tf32r(src[(size_t)r*DD + c0]);
    v.y = tf32r(src[(size_t)r*DD + c0+4]);
    dst[i] = v;
}
__global__ void sumsq_kernel(const float* __restrict__ x, float* __restrict__ o, int rows){
    if(blockIdx.x==0 && threadIdx.x==0) g_cnt = 0;
    int row = blockIdx.x*(blockDim.x>>5) + (threadIdx.x>>5); if(row>=rows) return;
    int lane = threadIdx.x&31; const float* p = x + (size_t)row*DD; float s=0.f;
    #pragma unroll
    for(int c=lane;c<DD;c+=32){ float v=p[c]; s+=v*v; }
    #pragma unroll
    for(int ofs=16;ofs;ofs>>=1) s+=__shfl_down_sync(0xffffffffu,s,ofs);
    if(!lane) o[row]=s;
}

__device__ __forceinline__ void issue_stage(uint32_t sb, int it, int t0, int tid){
    const int nt = it>>3, dc = it&7;
    const uint32_t tb = sb + (uint32_t)(it&3)*STGB;
    #pragma unroll
    for(int i=0;i<4;i++){
        int idx = tid + i*256;                       // A: 1024 granules
        int tl = idx>>7, ks = (idx>>5)&3, lane = idx&31;
        const float4* src = g_xp + ((size_t)(t0+tl)*32 + dc*4+ks)*32 + lane;
        CP16(tb + idx*16, src);
    }
    #pragma unroll
    for(int i=0;i<4;i++){
        int idx = tid + i*256;                       // B: 1024 granules
        int ntl = idx>>6, ks = (idx>>4)&3, j = idx&15;
        const float2* src = g_ep + ((size_t)(nt*16+ntl)*32 + dc*4+ks)*32 + 2*j;
        CP16(tb + 16384 + idx*16, src);
    }
    CP_COMMIT();
}

// ---- phase 1: 1-pass tf32 GEMM + min1/min2 + flagging ----
__global__ void __launch_bounds__(256,1) vq_phase1(
    const float* __restrict__ E, const float* __restrict__ esq,
    float* __restrict__ outq, float* __restrict__ outi)
{
    extern __shared__ char smem[];
    const uint32_t sb = s2u(smem);
    const int tid = threadIdx.x, wid = tid>>5, lane = tid&31;
    const int r = lane>>2, c = lane&3;
    const int wm = wid&1, wn = wid>>1;
    const int m0 = blockIdx.x*BM, t0 = blockIdx.x*8;

    float m1[8], m2[8]; int i1[8];
    #pragma unroll
    for(int i=0;i<8;i++){ m1[i]=3.4e38f; m2[i]=3.4e38f; i1[i]=0; }

    issue_stage(sb,0,t0,tid);
    issue_stage(sb,1,t0,tid);
    issue_stage(sb,2,t0,tid);

    for(int nt=0; nt<NNT; nt++){
        float acc[4][4][4];
        #pragma unroll
        for(int m=0;m<4;m++)
            #pragma unroll
            for(int n=0;n<4;n++){ acc[m][n][0]=0.f;acc[m][n][1]=0.f;acc[m][n][2]=0.f;acc[m][n][3]=0.f; }

        for(int dc=0; dc<8; dc++){
            const int it = nt*8 + dc;
            if(it < NIT-2)      { CP_WAIT(2); }
            else if(it == NIT-2){ CP_WAIT(1); }
            else                { CP_WAIT(0); }
            __syncthreads();
            if(it+3 < NIT) issue_stage(sb, it+3, t0, tid);
            const char* stp = smem + (size_t)(it&3)*STGB;

            #pragma unroll
            for(int ks=0; ks<4; ks++){
                float4 af[4]; float2 bf[4];
                #pragma unroll
                for(int m=0;m<4;m++)
                    af[m] = *(const float4*)(stp + ((wm*4+m)*4+ks)*512 + lane*16);
                #pragma unroll
                for(int n=0;n<4;n++)
                    bf[n] = *(const float2*)(stp + 16384 + ((wn*4+n)*4+ks)*256 + lane*8);
                #pragma unroll
                for(int m=0;m<4;m++)
                    #pragma unroll
                    for(int n=0;n<4;n++)
                        mma8(acc[m][n], (const uint32_t*)&af[m], (const uint32_t*)&bf[n]);
            }
        }
        #pragma unroll
        for(int m=0;m<4;m++){
            const int rl=2*m, rh=2*m+1;
            #pragma unroll
            for(int n=0;n<4;n++){
                int colb = nt*BN + wn*32 + n*8 + 2*c;
                float e0 = __ldg(esq+colb), e1 = __ldg(esq+colb+1);
                float d;
                d = e0 - 2.f*acc[m][n][0];
                if(d<m1[rl]){m2[rl]=m1[rl];m1[rl]=d;i1[rl]=colb;} else if(d<m2[rl]) m2[rl]=d;
                d = e1 - 2.f*acc[m][n][1];
                if(d<m1[rl]){m2[rl]=m1[rl];m1[rl]=d;i1[rl]=colb+1;} else if(d<m2[rl]) m2[rl]=d;
                d = e0 - 2.f*acc[m][n][2];
                if(d<m1[rh]){m2[rh]=m1[rh];m1[rh]=d;i1[rh]=colb;} else if(d<m2[rh]) m2[rh]=d;
                d = e1 - 2.f*acc[m][n][3];
                if(d<m1[rh]){m2[rh]=m1[rh];m1[rh]=d;i1[rh]=colb+1;} else if(d<m2[rh]) m2[rh]=d;
            }
        }
    }

    float* s_m1 = (float*)(smem + SBD);
    float* s_m2 = (float*)(smem + SB2);
    int*   s_i1 = (int*)(smem + SII);
    int*   s_idx= (int*)(smem + SIDX);
    __syncthreads();
    #pragma unroll
    for(int i=0;i<8;i++){
        int row  = wm*64 + (i>>1)*16 + r + (i&1)*8;
        int slot = wn*4 + c;
        s_m1[row*16+slot] = m1[i];
        s_m2[row*16+slot] = m2[i];
        s_i1[row*16+slot] = i1[i];
    }
    __syncthreads();
    if(tid < 128){
        float bd = 3.4e38f; int bi = 0, tw = 0;
        #pragma unroll
        for(int t=0;t<16;t++){
            float d = s_m1[tid*16+t]; int ii = s_i1[tid*16+t];
            if(d<bd || (d==bd && ii<bi)){ bd=d; bi=ii; tw=t; }
        }
        float b2 = 3.4e38f;
        #pragma unroll
        for(int t=0;t<16;t++){
            float v = (t==tw) ? s_m2[tid*16+t] : s_m1[tid*16+t];
            b2 = fminf(b2, v);
        }
        s_idx[tid] = bi;
        outi[m0+tid] = (float)bi;
        if(b2 - bd < FLAG_T){
            g_best[m0+tid] = 0xFFFFFFFFFFFFFFFFull;
            int pos = atomicAdd(&g_cnt, 1);
            if(pos < FLAG_CAP) g_flag[pos] = m0 + tid;
        }
    }
    __syncthreads();
    for(int f=tid; f<BM*(DD/4); f+=256){
        int rr = f>>6, c4 = f&63;
        float4 v = *(const float4*)(E + (size_t)s_idx[rr]*DD + c4*4);
        *(float4*)(outq + (size_t)(m0+rr)*DD + c4*4) = v;
    }
}

// ---- phase 2: exact fp32 rescore, K-split, atomicMin merge ----
__global__ void __launch_bounds__(128) vq_phase2(
    const float* __restrict__ X, const float* __restrict__ E, const float* __restrict__ esq)
{
    int cnt = g_cnt; if(cnt > FLAG_CAP) cnt = FLAG_CAP;
    const int rb = blockIdx.x;
    if(rb*P2M >= cnt) return;
    const int k0 = blockIdx.y * BN;
    __shared__ float Xs[16][P2M];
    __shared__ float Es[16][BN];
    __shared__ int rows[P2M];
    __shared__ float s_bd[16][P2M];
    __shared__ int   s_bi[16][P2M];
    const int tid = threadIdx.x;
    const int tx = tid&15, ty = tid>>4;
    if(tid < P2M){
        int fi = rb*P2M + tid; if(fi >= cnt) fi = cnt-1;
        rows[tid] = g_flag[fi];
    }
    __syncthreads();

    float acc[8][8];
    #pragma unroll
    for(int i=0;i<8;i++)
        #pragma unroll
        for(int j=0;j<8;j++) acc[i][j]=0.f;

    for(int d0=0; d0<DD; d0+=16){
        #pragma unroll
        for(int l=0;l<2;l++){
            int f = tid + l*128, rr = f>>2, c4 = f&3;
            float4 v = *(const float4*)(X + (size_t)rows[rr]*DD + d0 + c4*4);
            Xs[c4*4+0][rr]=v.x; Xs[c4*4+1][rr]=v.y; Xs[c4*4+2][rr]=v.z; Xs[c4*4+3][rr]=v.w;
        }
        #pragma unroll
        for(int l=0;l<4;l++){
            int f = tid + l*128, rr = f>>2, c4 = f&3;
            float4 v = *(const float4*)(E + (size_t)(k0+rr)*DD + d0 + c4*4);
            Es[c4*4+0][rr]=v.x; Es[c4*4+1][rr]=v.y; Es[c4*4+2][rr]=v.z; Es[c4*4+3][rr]=v.w;
        }
        __syncthreads();
        #pragma unroll
        for(int kk=0;kk<16;kk++){
            float xr[8], er[8];
            #pragma unroll
            for(int i=0;i<8;i++) xr[i]=Xs[kk][ty*8+i];
            #pragma unroll
            for(int j=0;j<8;j++) er[j]=Es[kk][tx*8+j];
            #pragma unroll
            for(int i=0;i<8;i++)
                #pragma unroll
                for(int j=0;j<8;j++) acc[i][j]=fmaf(xr[i],er[j],acc[i][j]);
        }
        __syncthreads();
    }
    float bd[8]; int bi[8];
    #pragma unroll
    for(int i=0;i<8;i++){ bd[i]=3.4e38f; bi[i]=0; }
    #pragma unroll
    for(int i=0;i<8;i++)
        #pragma unroll
        for(int j=0;j<8;j++){
            int col = k0 + tx*8 + j;
            float d = __ldg(esq+col) - 2.f*acc[i][j];
            if(d < bd[i]){ bd[i]=d; bi[i]=col; }
        }
    #pragma unroll
    for(int i=0;i<8;i++){ s_bd[tx][ty*8+i]=bd[i]; s_bi[tx][ty*8+i]=bi[i]; }
    __syncthreads();
    if(tid < P2M){
        float b = s_bd[0][tid]; int ii = s_bi[0][tid];
        #pragma unroll
        for(int t=1;t<16;t++){
            float d = s_bd[t][tid]; int jj = s_bi[t][tid];
            if(d<b || (d==b && jj<ii)){ b=d; ii=jj; }
        }
        if(rb*P2M + tid < cnt){
            uint32_t u = __float_as_uint(b);
            u = (u & 0x80000000u) ? ~u : (u | 0x80000000u);
            unsigned long long key = ((unsigned long long)u << 32) | (unsigned)ii;
            atomicMin(&g_best[rows[tid]], key);
        }
    }
}

// ---- phase 3: write back flagged rows ----
__global__ void __launch_bounds__(256) vq_phase3(
    const float* __restrict__ E, float* __restrict__ outq, float* __restrict__ outi)
{
    int cnt = g_cnt; if(cnt > FLAG_CAP) cnt = FLAG_CAP;
    int i = blockIdx.x*8 + (threadIdx.x>>5);
    if(i >= cnt) return;
    int lane = threadIdx.x&31;
    int row = g_flag[i];
    int bi = (int)(g_best[row] & 0xFFFFFFFFull);
    if(lane==0) outi[row] = (float)bi;
    float4 v0 = *(const float4*)(E + (size_t)bi*DD + lane*8);
    float4 v1 = *(const float4*)(E + (size_t)bi*DD + lane*8 + 4);
    *(float4*)(outq + (size_t)row*DD + lane*8)     = v0;
    *(float4*)(outq + (size_t)row*DD + lane*8 + 4) = v1;
}

extern "C" void kernel_launch(void* const* d_in, const int* in_sizes, int n_in,
                              void* d_out, int out_size) {
    const float* X = (const float*)d_in[0];
    const float* E = (const float*)d_in[1];

    float4* xp; float2* ep; float* esq;
    cudaGetSymbolAddress((void**)&xp, g_xp);
    cudaGetSymbolAddress((void**)&ep, g_ep);
    cudaGetSymbolAddress((void**)&esq, g_esq);

    packA<<<NTOK/16*32*32/256, 256>>>(X, xp);
    packB<<<KCB/8*32*32/256, 256>>>(E, ep);
    sumsq_kernel<<<KCB/8, 256>>>(E, esq, KCB);   // also zeroes g_cnt

    float* outq = (float*)d_out;
    float* outi = (float*)d_out + (size_t)NTOK*DD;

    cudaFuncSetAttribute(vq_phase1, cudaFuncAttributeMaxDynamicSharedMemorySize, SMEMSZ);
    vq_phase1<<<NTOK/BM, 256, SMEMSZ>>>(E, esq, outq, outi);
    vq_phase2<<<dim3(FLAG_CAP/P2M, KCB/BN), 128>>>(X, E, esq);
    vq_phase3<<<FLAG_CAP/8, 256>>>(E, outq, outi);
}

// round 7
// speedup vs baseline: 2.7594x; 1.0806x over previous
#include <cuda_runtime.h>
#include <cstdint>

#define DD 256
#define NTOK 16384
#define KCB 8192
#define BM 128
#define BN 256
#define NNT (KCB/BN)     // 32
#define NIT (NNT*8)      // 256
#define STGB 49152       // 16KB A + 32KB B
#define SMEMSZ (4*STGB)  // 192KB; epilogue overlays stage 0
#define FLAG_T 0.12f
#define FLAG_CAP 4096
#define P2M 64

__device__ __align__(128) float4 g_xp[NTOK/16*32*32];
__device__ __align__(128) float2 g_ep[KCB/8*32*32];
__device__ __align__(128) float g_esq[KCB];
__device__ unsigned long long g_best[NTOK];
__device__ int g_flag[FLAG_CAP];
__device__ int g_cnt;

#define CP16(d,s)   asm volatile("cp.async.cg.shared.global [%0], [%1], 16;"::"r"(d),"l"(s):"memory")
#define CP_COMMIT() asm volatile("cp.async.commit_group;":::"memory")
#define CP_WAIT(n)  asm volatile("cp.async.wait_group %0;"::"n"(n):"memory")

__device__ __forceinline__ uint32_t s2u(const void* p){
    uint32_t a; asm("{ .reg .u64 t; cvta.to.shared.u64 t, %1; cvt.u32.u64 %0, t; }":"=r"(a):"l"(p)); return a;
}
__device__ __forceinline__ void mma8(float* d, const uint32_t* a, const uint32_t* b){
    asm("mma.sync.aligned.m16n8k8.row.col.f32.tf32.tf32.f32 "
        "{%0,%1,%2,%3}, {%4,%5,%6,%7}, {%8,%9}, {%0,%1,%2,%3};"
        : "+f"(d[0]),"+f"(d[1]),"+f"(d[2]),"+f"(d[3])
        : "r"(a[0]),"r"(a[1]),"r"(a[2]),"r"(a[3]),"r"(b[0]),"r"(b[1]));
}
__device__ __forceinline__ float tf32r(float x){
    uint32_t b; asm("cvt.rna.tf32.f32 %0, %1;":"=r"(b):"f"(x)); return __uint_as_float(b);
}

// ---- prep: pack A fragments (per 16x8 tile, lane-major float4) ----
__global__ void packA(const float* __restrict__ src, float4* __restrict__ dst){
    int i = blockIdx.x*blockDim.x + threadIdx.x;
    int lane = i&31, kc = (i>>5)&31, t = i>>10;
    int gr = lane>>2, gc = lane&3;
    int r0 = t*16+gr, c0 = kc*8+gc;
    float4 v;
    v.x = tf32r(src[(size_t)r0*DD + c0]);
    v.y = tf32r(src[(size_t)(r0+8)*DD + c0]);
    v.z = tf32r(src[(size_t)r0*DD + c0+4]);
    v.w = tf32r(src[(size_t)(r0+8)*DD + c0+4]);
    dst[i] = v;
}
// ---- prep: pack B fragments (per 8x8 tile, lane-major float2) ----
__global__ void packB(const float* __restrict__ src, float2* __restrict__ dst){
    int i = blockIdx.x*blockDim.x + threadIdx.x;
    int lane = i&31, kc = (i>>5)&31, n8 = i>>10;
    int gr = lane>>2, gc = lane&3;
    int r = n8*8+gr, c0 = kc*8+gc;
    float2 v;
    v.x = tf32r(src[(size_t)r*DD + c0]);
    v.y = tf32r(src[(size_t)r*DD + c0+4]);
    dst[i] = v;
}
__global__ void sumsq_kernel(const float* __restrict__ x, float* __restrict__ o, int rows){
    if(blockIdx.x==0 && threadIdx.x==0) g_cnt = 0;
    int row = blockIdx.x*(blockDim.x>>5) + (threadIdx.x>>5); if(row>=rows) return;
    int lane = threadIdx.x&31; const float* p = x + (size_t)row*DD; float s=0.f;
    #pragma unroll
    for(int c=lane;c<DD;c+=32){ float v=p[c]; s+=v*v; }
    #pragma unroll
    for(int ofs=16;ofs;ofs>>=1) s+=__shfl_down_sync(0xffffffffu,s,ofs);
    if(!lane) o[row]=s;
}

__device__ __forceinline__ void issue_stage(uint32_t sb, int it, int t0, int tid){
    const int nt = it>>3, dc = it&7;
    const uint32_t tb = sb + (uint32_t)(it&3)*STGB;
    #pragma unroll
    for(int i=0;i<4;i++){                            // A: 1024 granules (16KB)
        int idx = tid + i*256;
        int tl = idx>>7, ks = (idx>>5)&3, lane = idx&31;
        const float4* src = g_xp + ((size_t)(t0+tl)*32 + dc*4+ks)*32 + lane;
        CP16(tb + idx*16, src);
    }
    #pragma unroll
    for(int i=0;i<8;i++){                            // B: 2048 granules (32KB)
        int idx = tid + i*256;
        int ntl = idx>>6, ks = (idx>>4)&3, j = idx&15;
        const float2* src = g_ep + ((size_t)(nt*32+ntl)*32 + dc*4+ks)*32 + 2*j;
        CP16(tb + 16384 + idx*16, src);
    }
    CP_COMMIT();
}

// ---- phase 1: 1-pass tf32 GEMM (warp tile 64x64) + min1/min2 + flagging ----
__global__ void __launch_bounds__(256,1) vq_phase1(
    const float* __restrict__ E, const float* __restrict__ esq,
    float* __restrict__ outq, float* __restrict__ outi)
{
    extern __shared__ char smem[];
    const uint32_t sb = s2u(smem);
    const int tid = threadIdx.x, wid = tid>>5, lane = tid&31;
    const int r = lane>>2, c = lane&3;
    const int wm = wid&1, wn = wid>>1;     // 2 x 4 warp grid, warp tile 64x64
    const int m0 = blockIdx.x*BM, t0 = blockIdx.x*8;

    float m1[8], m2[8]; int i1[8];
    #pragma unroll
    for(int i=0;i<8;i++){ m1[i]=3.4e38f; m2[i]=3.4e38f; i1[i]=0; }

    issue_stage(sb,0,t0,tid);
    issue_stage(sb,1,t0,tid);
    issue_stage(sb,2,t0,tid);

    for(int nt=0; nt<NNT; nt++){
        float acc[4][8][4];
        #pragma unroll
        for(int m=0;m<4;m++)
            #pragma unroll
            for(int n=0;n<8;n++){ acc[m][n][0]=0.f;acc[m][n][1]=0.f;acc[m][n][2]=0.f;acc[m][n][3]=0.f; }

        for(int dc=0; dc<8; dc++){
            const int it = nt*8 + dc;
            if(it < NIT-2)      { CP_WAIT(2); }
            else if(it == NIT-2){ CP_WAIT(1); }
            else                { CP_WAIT(0); }
            __syncthreads();
            if(it+3 < NIT) issue_stage(sb, it+3, t0, tid);
            const char* stp = smem + (size_t)(it&3)*STGB;

            #pragma unroll
            for(int ks=0; ks<4; ks++){
                float4 af[4]; float2 bf[8];
                #pragma unroll
                for(int m=0;m<4;m++)
                    af[m] = *(const float4*)(stp + ((wm*4+m)*4+ks)*512 + lane*16);
                #pragma unroll
                for(int n=0;n<8;n++)
                    bf[n] = *(const float2*)(stp + 16384 + ((wn*8+n)*4+ks)*256 + lane*8);
                #pragma unroll
                for(int m=0;m<4;m++)
                    #pragma unroll
                    for(int n=0;n<8;n++)
                        mma8(acc[m][n], (const uint32_t*)&af[m], (const uint32_t*)&bf[n]);
            }
        }
        #pragma unroll
        for(int m=0;m<4;m++){
            const int rl=2*m, rh=2*m+1;
            #pragma unroll
            for(int n=0;n<8;n++){
                int colb = nt*BN + wn*64 + n*8 + 2*c;
                float e0 = __ldg(esq+colb), e1 = __ldg(esq+colb+1);
                float d;
                d = e0 - 2.f*acc[m][n][0];
                if(d<m1[rl]){m2[rl]=m1[rl];m1[rl]=d;i1[rl]=colb;} else if(d<m2[rl]) m2[rl]=d;
                d = e1 - 2.f*acc[m][n][1];
                if(d<m1[rl]){m2[rl]=m1[rl];m1[rl]=d;i1[rl]=colb+1;} else if(d<m2[rl]) m2[rl]=d;
                d = e0 - 2.f*acc[m][n][2];
                if(d<m1[rh]){m2[rh]=m1[rh];m1[rh]=d;i1[rh]=colb;} else if(d<m2[rh]) m2[rh]=d;
                d = e1 - 2.f*acc[m][n][3];
                if(d<m1[rh]){m2[rh]=m1[rh];m1[rh]=d;i1[rh]=colb+1;} else if(d<m2[rh]) m2[rh]=d;
            }
        }
    }

    // epilogue reduction overlays the (now dead) stage buffers
    float* s_m1 = (float*)(smem);
    float* s_m2 = (float*)(smem + 8192);
    int*   s_i1 = (int*)(smem + 16384);
    int*   s_idx= (int*)(smem + 24576);
    __syncthreads();
    #pragma unroll
    for(int i=0;i<8;i++){
        int row  = wm*64 + (i>>1)*16 + r + (i&1)*8;
        int slot = wn*4 + c;
        s_m1[row*16+slot] = m1[i];
        s_m2[row*16+slot] = m2[i];
        s_i1[row*16+slot] = i1[i];
    }
    __syncthreads();
    if(tid < 128){
        float bd = 3.4e38f; int bi = 0, tw = 0;
        #pragma unroll
        for(int t=0;t<16;t++){
            float d = s_m1[tid*16+t]; int ii = s_i1[tid*16+t];
            if(d<bd || (d==bd && ii<bi)){ bd=d; bi=ii; tw=t; }
        }
        float b2 = 3.4e38f;
        #pragma unroll
        for(int t=0;t<16;t++){
            float v = (t==tw) ? s_m2[tid*16+t] : s_m1[tid*16+t];
            b2 = fminf(b2, v);
        }
        s_idx[tid] = bi;
        outi[m0+tid] = (float)bi;
        if(b2 - bd < FLAG_T){
            g_best[m0+tid] = 0xFFFFFFFFFFFFFFFFull;
            int pos = atomicAdd(&g_cnt, 1);
            if(pos < FLAG_CAP) g_flag[pos] = m0 + tid;
        }
    }
    __syncthreads();
    for(int f=tid; f<BM*(DD/4); f+=256){
        int rr = f>>6, c4 = f&63;
        float4 v = *(const float4*)(E + (size_t)s_idx[rr]*DD + c4*4);
        *(float4*)(outq + (size_t)(m0+rr)*DD + c4*4) = v;
    }
}

// ---- phase 2: exact fp32 rescore, K-split, atomicMin merge ----
__global__ void __launch_bounds__(128) vq_phase2(
    const float* __restrict__ X, const float* __restrict__ E, const float* __restrict__ esq)
{
    int cnt = g_cnt; if(cnt > FLAG_CAP) cnt = FLAG_CAP;
    const int rb = blockIdx.x;
    if(rb*P2M >= cnt) return;
    const int k0 = blockIdx.y * 128;
    __shared__ float Xs[16][P2M];
    __shared__ float Es[16][128];
    __shared__ int rows[P2M];
    __shared__ float s_bd[16][P2M];
    __shared__ int   s_bi[16][P2M];
    const int tid = threadIdx.x;
    const int tx = tid&15, ty = tid>>4;
    if(tid < P2M){
        int fi = rb*P2M + tid; if(fi >= cnt) fi = cnt-1;
        rows[tid] = g_flag[fi];
    }
    __syncthreads();

    float acc[8][8];
    #pragma unroll
    for(int i=0;i<8;i++)
        #pragma unroll
        for(int j=0;j<8;j++) acc[i][j]=0.f;

    for(int d0=0; d0<DD; d0+=16){
        #pragma unroll
        for(int l=0;l<2;l++){
            int f = tid + l*128, rr = f>>2, c4 = f&3;
            float4 v = *(const float4*)(X + (size_t)rows[rr]*DD + d0 + c4*4);
            Xs[c4*4+0][rr]=v.x; Xs[c4*4+1][rr]=v.y; Xs[c4*4+2][rr]=v.z; Xs[c4*4+3][rr]=v.w;
        }
        #pragma unroll
        for(int l=0;l<4;l++){
            int f = tid + l*128, rr = f>>2, c4 = f&3;
            float4 v = *(const float4*)(E + (size_t)(k0+rr)*DD + d0 + c4*4);
            Es[c4*4+0][rr]=v.x; Es[c4*4+1][rr]=v.y; Es[c4*4+2][rr]=v.z; Es[c4*4+3][rr]=v.w;
        }
        __syncthreads();
        #pragma unroll
        for(int kk=0;kk<16;kk++){
            float xr[8], er[8];
            #pragma unroll
            for(int i=0;i<8;i++) xr[i]=Xs[kk][ty*8+i];
            #pragma unroll
            for(int j=0;j<8;j++) er[j]=Es[kk][tx*8+j];
            #pragma unroll
            for(int i=0;i<8;i++)
                #pragma unroll
                for(int j=0;j<8;j++) acc[i][j]=fmaf(xr[i],er[j],acc[i][j]);
        }
        __syncthreads();
    }
    float bd[8]; int bi[8];
    #pragma unroll
    for(int i=0;i<8;i++){ bd[i]=3.4e38f; bi[i]=0; }
    #pragma unroll
    for(int i=0;i<8;i++)
        #pragma unroll
        for(int j=0;j<8;j++){
            int col = k0 + tx*8 + j;
            float d = __ldg(esq+col) - 2.f*acc[i][j];
            if(d < bd[i]){ bd[i]=d; bi[i]=col; }
        }
    #pragma unroll
    for(int i=0;i<8;i++){ s_bd[tx][ty*8+i]=bd[i]; s_bi[tx][ty*8+i]=bi[i]; }
    __syncthreads();
    if(tid < P2M){
        float b = s_bd[0][tid]; int ii = s_bi[0][tid];
        #pragma unroll
        for(int t=1;t<16;t++){
            float d = s_bd[t][tid]; int jj = s_bi[t][tid];
            if(d<b || (d==b && jj<ii)){ b=d; ii=jj; }
        }
        if(rb*P2M + tid < cnt){
            uint32_t u = __float_as_uint(b);
            u = (u & 0x80000000u) ? ~u : (u | 0x80000000u);
            unsigned long long key = ((unsigned long long)u << 32) | (unsigned)ii;
            atomicMin(&g_best[rows[tid]], key);
        }
    }
}

// ---- phase 3: write back flagged rows ----
__global__ void __launch_bounds__(256) vq_phase3(
    const float* __restrict__ E, float* __restrict__ outq, float* __restrict__ outi)
{
    int cnt = g_cnt; if(cnt > FLAG_CAP) cnt = FLAG_CAP;
    int i = blockIdx.x*8 + (threadIdx.x>>5);
    if(i >= cnt) return;
    int lane = threadIdx.x&31;
    int row = g_flag[i];
    int bi = (int)(g_best[row] & 0xFFFFFFFFull);
    if(lane==0) outi[row] = (float)bi;
    float4 v0 = *(const float4*)(E + (size_t)bi*DD + lane*8);
    float4 v1 = *(const float4*)(E + (size_t)bi*DD + lane*8 + 4);
    *(float4*)(outq + (size_t)row*DD + lane*8)     = v0;
    *(float4*)(outq + (size_t)row*DD + lane*8 + 4) = v1;
}

extern "C" void kernel_launch(void* const* d_in, const int* in_sizes, int n_in,
                              void* d_out, int out_size) {
    const float* X = (const float*)d_in[0];
    const float* E = (const float*)d_in[1];

    float4* xp; float2* ep; float* esq;
    cudaGetSymbolAddress((void**)&xp, g_xp);
    cudaGetSymbolAddress((void**)&ep, g_ep);
    cudaGetSymbolAddress((void**)&esq, g_esq);

    packA<<<NTOK/16*32*32/256, 256>>>(X, xp);
    packB<<<KCB/8*32*32/256, 256>>>(E, ep);
    sumsq_kernel<<<KCB/8, 256>>>(E, esq, KCB);   // also zeroes g_cnt

    float* outq = (float*)d_out;
    float* outi = (float*)d_out + (size_t)NTOK*DD;

    cudaFuncSetAttribute(vq_phase1, cudaFuncAttributeMaxDynamicSharedMemorySize, SMEMSZ);
    vq_phase1<<<NTOK/BM, 256, SMEMSZ>>>(E, esq, outq, outi);
    vq_phase2<<<dim3(FLAG_CAP/P2M, KCB/128), 128>>>(X, E, esq);
    vq_phase3<<<FLAG_CAP/8, 256>>>(E, outq, outi);
}

// round 8
// speedup vs baseline: 3.2230x; 1.1680x over previous
#include <cuda_runtime.h>
#include <cstdint>

#define DD 256
#define NTOK 16384
#define KCB 8192
#define BM 128
#define BN 256
#define NNT (KCB/BN)     // 32
#define NIT (NNT*8)      // 256
#define STGB 49152       // 16KB A + 32KB B
#define BARS (4*STGB)    // barrier block after stages
#define SMEMSZ (BARS + 128)
#define FLAG_T 0.12f
#define FLAG_CAP 4096
#define P2M 64

// A packed: [mb 0..127][dc 0..7] -> 16KB contiguous ([tl 0..7][ks 0..3][lane 0..31] float4)
__device__ __align__(128) float4 g_xp[NTOK*DD/4];
// B packed: [nt 0..31][dc 0..7] -> 32KB contiguous ([ntl 0..31][ks 0..3][lane 0..31] float2)
__device__ __align__(128) float2 g_ep[KCB*DD/2];
__device__ __align__(128) float g_esq[KCB];
__device__ unsigned long long g_best[NTOK];
__device__ int g_flag[FLAG_CAP];
__device__ int g_cnt;

__device__ __forceinline__ uint32_t s2u(const void* p){
    uint32_t a; asm("{ .reg .u64 t; cvta.to.shared.u64 t, %1; cvt.u32.u64 %0, t; }":"=r"(a):"l"(p)); return a;
}
#define MBAR_INIT(a,c) asm volatile("mbarrier.init.shared.b64 [%0], %1;"::"r"(a),"r"(c):"memory")
#define MBAR_ARRIVE(a) asm volatile("mbarrier.arrive.shared.b64 _, [%0];"::"r"(a):"memory")
#define MBAR_EXPECT_TX(a,tx) asm volatile("mbarrier.arrive.expect_tx.shared.b64 _, [%0], %1;"::"r"(a),"r"(tx):"memory")
#define MBAR_WAIT(a,p) do{ uint32_t _m=(a),_p=(p),_d; \
    asm volatile("{\n\t.reg .pred q;\n\tmbarrier.try_wait.parity.acquire.cta.shared::cta.b64 q,[%1],%2;\n\tselp.b32 %0,1,0,q;\n\t}":"=r"(_d):"r"(_m),"r"(_p):"memory"); \
    if(!_d){ asm volatile("{\n\t.reg .pred q;\n\tW%=:\n\tmbarrier.try_wait.parity.acquire.cta.shared::cta.b64 q,[%0],%1,0x989680;\n\t@q bra.uni DN%=;\n\tbra.uni W%=;\n\tDN%=:\n\t}"::"r"(_m),"r"(_p):"memory"); } }while(0)
#define BULK_G2S(d,s,n,mb) asm volatile( \
    "cp.async.bulk.shared::cluster.global.mbarrier::complete_tx::bytes [%0], [%1], %2, [%3];" \
    :: "r"((uint32_t)(d)),"l"(s),"r"((uint32_t)(n)),"r"((uint32_t)(mb)) : "memory")

__device__ __forceinline__ void mma8(float* d, const uint32_t* a, const uint32_t* b){
    asm("mma.sync.aligned.m16n8k8.row.col.f32.tf32.tf32.f32 "
        "{%0,%1,%2,%3}, {%4,%5,%6,%7}, {%8,%9}, {%0,%1,%2,%3};"
        : "+f"(d[0]),"+f"(d[1]),"+f"(d[2]),"+f"(d[3])
        : "r"(a[0]),"r"(a[1]),"r"(a[2]),"r"(a[3]),"r"(b[0]),"r"(b[1]));
}
__device__ __forceinline__ float tf32r(float x){
    uint32_t b; asm("cvt.rna.tf32.f32 %0, %1;":"=r"(b):"f"(x)); return __uint_as_float(b);
}

// ---- prep: pack A so each (mb,dc) block of 16KB is contiguous ----
__global__ void packA(const float* __restrict__ src, float4* __restrict__ dst){
    int i = blockIdx.x*blockDim.x + threadIdx.x;      // NTOK*DD/4 threads
    int lane = i&31, ks = (i>>5)&3, tl = (i>>7)&7, dc = (i>>10)&7, mb = i>>13;
    int gr = lane>>2, gc = lane&3;
    int r0 = (mb*8+tl)*16 + gr, c0 = (dc*4+ks)*8 + gc;
    float4 v;
    v.x = tf32r(src[(size_t)r0*DD + c0]);
    v.y = tf32r(src[(size_t)(r0+8)*DD + c0]);
    v.z = tf32r(src[(size_t)r0*DD + c0+4]);
    v.w = tf32r(src[(size_t)(r0+8)*DD + c0+4]);
    dst[i] = v;
}
// ---- prep: pack B so each (nt,dc) block of 32KB is contiguous ----
__global__ void packB(const float* __restrict__ src, float2* __restrict__ dst){
    int i = blockIdx.x*blockDim.x + threadIdx.x;      // KCB*DD/2 threads
    int lane = i&31, ks = (i>>5)&3, ntl = (i>>7)&31, dc = (i>>12)&7, nt = i>>15;
    int gr = lane>>2, gc = lane&3;
    int r = (nt*32+ntl)*8 + gr, c0 = (dc*4+ks)*8 + gc;
    float2 v;
    v.x = tf32r(src[(size_t)r*DD + c0]);
    v.y = tf32r(src[(size_t)r*DD + c0+4]);
    dst[i] = v;
}
__global__ void sumsq_kernel(const float* __restrict__ x, float* __restrict__ o, int rows){
    if(blockIdx.x==0 && threadIdx.x==0) g_cnt = 0;
    int row = blockIdx.x*(blockDim.x>>5) + (threadIdx.x>>5); if(row>=rows) return;
    int lane = threadIdx.x&31; const float* p = x + (size_t)row*DD; float s=0.f;
    #pragma unroll
    for(int c=lane;c<DD;c+=32){ float v=p[c]; s+=v*v; }
    #pragma unroll
    for(int ofs=16;ofs;ofs>>=1) s+=__shfl_down_sync(0xffffffffu,s,ofs);
    if(!lane) o[row]=s;
}

// ---- phase 1: bulk-copy pipelined tf32 GEMM + min1/min2 + flagging ----
__global__ void __launch_bounds__(256,1) vq_phase1(
    const float* __restrict__ E, const float* __restrict__ esq,
    float* __restrict__ outq, float* __restrict__ outi)
{
    extern __shared__ char smem[];
    const uint32_t sb = s2u(smem);
    const int tid = threadIdx.x, wid = tid>>5, lane = tid&31;
    const int r = lane>>2, c = lane&3;
    const int wm = wid&1, wn = wid>>1;     // 2 x 4 warp grid, warp tile 64x64
    const int m0 = blockIdx.x*BM, mb = blockIdx.x;

    const uint32_t fullb  = sb + BARS;        // 4 x 8B
    const uint32_t emptyb = sb + BARS + 32;   // 4 x 8B

    if(tid==0){
        #pragma unroll
        for(int s=0;s<4;s++){ MBAR_INIT(fullb+s*8,1); MBAR_INIT(emptyb+s*8,8); }
    }
    __syncthreads();
    if(tid==0){
        #pragma unroll
        for(int j=0;j<3;j++){
            MBAR_EXPECT_TX(fullb+j*8, STGB);
            const char* srcA = (const char*)g_xp + ((size_t)(mb*8 + (j&7)))*16384;
            const char* srcB = (const char*)g_ep + ((size_t)((j>>3)*8 + (j&7)))*32768;
            BULK_G2S(sb + j*STGB,         srcA, 16384, fullb+j*8);
            BULK_G2S(sb + j*STGB + 16384, srcB, 32768, fullb+j*8);
        }
    }

    float m1[8], m2[8]; int i1[8];
    #pragma unroll
    for(int i=0;i<8;i++){ m1[i]=3.4e38f; m2[i]=3.4e38f; i1[i]=0; }

    for(int nt=0; nt<NNT; nt++){
        float acc[4][8][4];
        #pragma unroll
        for(int m=0;m<4;m++)
            #pragma unroll
            for(int n=0;n<8;n++){ acc[m][n][0]=0.f;acc[m][n][1]=0.f;acc[m][n][2]=0.f;acc[m][n][3]=0.f; }

        for(int dc=0; dc<8; dc++){
            const int it = nt*8 + dc;
            const int s = it&3;
            if(tid==0 && it+3 < NIT){
                const int j = it+3, sj = j&3;
                if(j>=4) MBAR_WAIT(emptyb+sj*8, ((j>>2)-1)&1);
                MBAR_EXPECT_TX(fullb+sj*8, STGB);
                const char* srcA = (const char*)g_xp + ((size_t)(mb*8 + (j&7)))*16384;
                const char* srcB = (const char*)g_ep + ((size_t)((j>>3)*8 + (j&7)))*32768;
                BULK_G2S(sb + sj*STGB,         srcA, 16384, fullb+sj*8);
                BULK_G2S(sb + sj*STGB + 16384, srcB, 32768, fullb+sj*8);
            }
            MBAR_WAIT(fullb+s*8, (it>>2)&1);
            const char* stp = smem + (size_t)s*STGB;

            #pragma unroll
            for(int ks=0; ks<4; ks++){
                float4 af[4]; float2 bf[8];
                #pragma unroll
                for(int m=0;m<4;m++)
                    af[m] = *(const float4*)(stp + ((wm*4+m)*4+ks)*512 + lane*16);
                #pragma unroll
                for(int n=0;n<8;n++)
                    bf[n] = *(const float2*)(stp + 16384 + ((wn*8+n)*4+ks)*256 + lane*8);
                #pragma unroll
                for(int m=0;m<4;m++)
                    #pragma unroll
                    for(int n=0;n<8;n++)
                        mma8(acc[m][n], (const uint32_t*)&af[m], (const uint32_t*)&bf[n]);
            }
            __syncwarp();
            if(lane==0) MBAR_ARRIVE(emptyb+s*8);
        }
        #pragma unroll
        for(int m=0;m<4;m++){
            const int rl=2*m, rh=2*m+1;
            #pragma unroll
            for(int n=0;n<8;n++){
                int colb = nt*BN + wn*64 + n*8 + 2*c;
                float e0 = __ldg(esq+colb), e1 = __ldg(esq+colb+1);
                float d;
                d = e0 - 2.f*acc[m][n][0];
                if(d<m1[rl]){m2[rl]=m1[rl];m1[rl]=d;i1[rl]=colb;} else if(d<m2[rl]) m2[rl]=d;
                d = e1 - 2.f*acc[m][n][1];
                if(d<m1[rl]){m2[rl]=m1[rl];m1[rl]=d;i1[rl]=colb+1;} else if(d<m2[rl]) m2[rl]=d;
                d = e0 - 2.f*acc[m][n][2];
                if(d<m1[rh]){m2[rh]=m1[rh];m1[rh]=d;i1[rh]=colb;} else if(d<m2[rh]) m2[rh]=d;
                d = e1 - 2.f*acc[m][n][3];
                if(d<m1[rh]){m2[rh]=m1[rh];m1[rh]=d;i1[rh]=colb+1;} else if(d<m2[rh]) m2[rh]=d;
            }
        }
    }

    // epilogue reduction overlays the (now dead) stage buffers
    float* s_m1 = (float*)(smem);
    float* s_m2 = (float*)(smem + 8192);
    int*   s_i1 = (int*)(smem + 16384);
    int*   s_idx= (int*)(smem + 24576);
    __syncthreads();
    #pragma unroll
    for(int i=0;i<8;i++){
        int row  = wm*64 + (i>>1)*16 + r + (i&1)*8;
        int slot = wn*4 + c;
        s_m1[row*16+slot] = m1[i];
        s_m2[row*16+slot] = m2[i];
        s_i1[row*16+slot] = i1[i];
    }
    __syncthreads();
    if(tid < 128){
        float bd = 3.4e38f; int bi = 0, tw = 0;
        #pragma unroll
        for(int t=0;t<16;t++){
            float d = s_m1[tid*16+t]; int ii = s_i1[tid*16+t];
            if(d<bd || (d==bd && ii<bi)){ bd=d; bi=ii; tw=t; }
        }
        float b2 = 3.4e38f;
        #pragma unroll
        for(int t=0;t<16;t++){
            float v = (t==tw) ? s_m2[tid*16+t] : s_m1[tid*16+t];
            b2 = fminf(b2, v);
        }
        s_idx[tid] = bi;
        outi[m0+tid] = (float)bi;
        if(b2 - bd < FLAG_T){
            g_best[m0+tid] = 0xFFFFFFFFFFFFFFFFull;
            int pos = atomicAdd(&g_cnt, 1);
            if(pos < FLAG_CAP) g_flag[pos] = m0 + tid;
        }
    }
    __syncthreads();
    for(int f=tid; f<BM*(DD/4); f+=256){
        int rr = f>>6, c4 = f&63;
        float4 v = *(const float4*)(E + (size_t)s_idx[rr]*DD + c4*4);
        *(float4*)(outq + (size_t)(m0+rr)*DD + c4*4) = v;
    }
}

// ---- phase 2: exact fp32 rescore, K-split, atomicMin merge ----
__global__ void __launch_bounds__(128) vq_phase2(
    const float* __restrict__ X, const float* __restrict__ E, const float* __restrict__ esq)
{
    int cnt = g_cnt; if(cnt > FLAG_CAP) cnt = FLAG_CAP;
    const int rb = blockIdx.x;
    if(rb*P2M >= cnt) return;
    const int k0 = blockIdx.y * 128;
    __shared__ float Xs[16][P2M];
    __shared__ float Es[16][128];
    __shared__ int rows[P2M];
    __shared__ float s_bd[16][P2M];
    __shared__ int   s_bi[16][P2M];
    const int tid = threadIdx.x;
    const int tx = tid&15, ty = tid>>4;
    if(tid < P2M){
        int fi = rb*P2M + tid; if(fi >= cnt) fi = cnt-1;
        rows[tid] = g_flag[fi];
    }
    __syncthreads();

    float acc[8][8];
    #pragma unroll
    for(int i=0;i<8;i++)
        #pragma unroll
        for(int j=0;j<8;j++) acc[i][j]=0.f;

    for(int d0=0; d0<DD; d0+=16){
        #pragma unroll
        for(int l=0;l<2;l++){
            int f = tid + l*128, rr = f>>2, c4 = f&3;
            float4 v = *(const float4*)(X + (size_t)rows[rr]*DD + d0 + c4*4);
            Xs[c4*4+0][rr]=v.x; Xs[c4*4+1][rr]=v.y; Xs[c4*4+2][rr]=v.z; Xs[c4*4+3][rr]=v.w;
        }
        #pragma unroll
        for(int l=0;l<4;l++){
            int f = tid + l*128, rr = f>>2, c4 = f&3;
            float4 v = *(const float4*)(E + (size_t)(k0+rr)*DD + d0 + c4*4);
            Es[c4*4+0][rr]=v.x; Es[c4*4+1][rr]=v.y; Es[c4*4+2][rr]=v.z; Es[c4*4+3][rr]=v.w;
        }
        __syncthreads();
        #pragma unroll
        for(int kk=0;kk<16;kk++){
            float xr[8], er[8];
            #pragma unroll
            for(int i=0;i<8;i++) xr[i]=Xs[kk][ty*8+i];
            #pragma unroll
            for(int j=0;j<8;j++) er[j]=Es[kk][tx*8+j];
            #pragma unroll
            for(int i=0;i<8;i++)
                #pragma unroll
                for(int j=0;j<8;j++) acc[i][j]=fmaf(xr[i],er[j],acc[i][j]);
        }
        __syncthreads();
    }
    float bd[8]; int bi[8];
    #pragma unroll
    for(int i=0;i<8;i++){ bd[i]=3.4e38f; bi[i]=0; }
    #pragma unroll
    for(int i=0;i<8;i++)
        #pragma unroll
        for(int j=0;j<8;j++){
            int col = k0 + tx*8 + j;
            float d = __ldg(esq+col) - 2.f*acc[i][j];
            if(d < bd[i]){ bd[i]=d; bi[i]=col; }
        }
    #pragma unroll
    for(int i=0;i<8;i++){ s_bd[tx][ty*8+i]=bd[i]; s_bi[tx][ty*8+i]=bi[i]; }
    __syncthreads();
    if(tid < P2M){
        float b = s_bd[0][tid]; int ii = s_bi[0][tid];
        #pragma unroll
        for(int t=1;t<16;t++){
            float d = s_bd[t][tid]; int jj = s_bi[t][tid];
            if(d<b || (d==b && jj<ii)){ b=d; ii=jj; }
        }
        if(rb*P2M + tid < cnt){
            uint32_t u = __float_as_uint(b);
            u = (u & 0x80000000u) ? ~u : (u | 0x80000000u);
            unsigned long long key = ((unsigned long long)u << 32) | (unsigned)ii;
            atomicMin(&g_best[rows[tid]], key);
        }
    }
}

// ---- phase 3: write back flagged rows ----
__global__ void __launch_bounds__(256) vq_phase3(
    const float* __restrict__ E, float* __restrict__ outq, float* __restrict__ outi)
{
    int cnt = g_cnt; if(cnt > FLAG_CAP) cnt = FLAG_CAP;
    int i = blockIdx.x*8 + (threadIdx.x>>5);
    if(i >= cnt) return;
    int lane = threadIdx.x&31;
    int row = g_flag[i];
    int bi = (int)(g_best[row] & 0xFFFFFFFFull);
    if(lane==0) outi[row] = (float)bi;
    float4 v0 = *(const float4*)(E + (size_t)bi*DD + lane*8);
    float4 v1 = *(const float4*)(E + (size_t)bi*DD + lane*8 + 4);
    *(float4*)(outq + (size_t)row*DD + lane*8)     = v0;
    *(float4*)(outq + (size_t)row*DD + lane*8 + 4) = v1;
}

extern "C" void kernel_launch(void* const* d_in, const int* in_sizes, int n_in,
                              void* d_out, int out_size) {
    const float* X = (const float*)d_in[0];
    const float* E = (const float*)d_in[1];

    float4* xp; float2* ep; float* esq;
    cudaGetSymbolAddress((void**)&xp, g_xp);
    cudaGetSymbolAddress((void**)&ep, g_ep);
    cudaGetSymbolAddress((void**)&esq, g_esq);

    packA<<<NTOK*DD/4/256, 256>>>(X, xp);
    packB<<<KCB*DD/2/256, 256>>>(E, ep);
    sumsq_kernel<<<KCB/8, 256>>>(E, esq, KCB);   // also zeroes g_cnt

    float* outq = (float*)d_out;
    float* outi = (float*)d_out + (size_t)NTOK*DD;

    cudaFuncSetAttribute(vq_phase1, cudaFuncAttributeMaxDynamicSharedMemorySize, SMEMSZ);
    vq_phase1<<<NTOK/BM, 256, SMEMSZ>>>(E, esq, outq, outi);
    vq_phase2<<<dim3(FLAG_CAP/P2M, KCB/128), 128>>>(X, E, esq);
    vq_phase3<<<FLAG_CAP/8, 256>>>(E, outq, outi);
}

// round 9
// speedup vs baseline: 3.7454x; 1.1621x over previous
#include <cuda_runtime.h>
#include <cstdint>

#define DD 256
#define NTOK 16384
#define KCB 8192
#define BM 128
#define BN 256
#define NNT (KCB/BN)     // 32
#define NIT (NNT*8)      // 256
#define STGB 49152       // 16KB A + 32KB B
#define BARS (4*STGB)
#define SMEMSZ (BARS + 128)
#define NTHR 512
#define FLAG_T 0.12f
#define FLAG_CAP 4096
#define P2M 64

// A packed: [mb 0..127][dc 0..7] -> 16KB contiguous ([tl 0..7][ks 0..3][lane 0..31] float4)
__device__ __align__(128) float4 g_xp[NTOK*DD/4];
// B packed: [nt 0..31][dc 0..7] -> 32KB contiguous ([ntl 0..31][ks 0..3][lane 0..31] float2)
__device__ __align__(128) float2 g_ep[KCB*DD/2];
__device__ __align__(128) float g_esq[KCB];
__device__ unsigned long long g_best[NTOK];
__device__ int g_flag[FLAG_CAP];
__device__ int g_cnt;

__device__ __forceinline__ uint32_t s2u(const void* p){
    uint32_t a; asm("{ .reg .u64 t; cvta.to.shared.u64 t, %1; cvt.u32.u64 %0, t; }":"=r"(a):"l"(p)); return a;
}
#define MBAR_INIT(a,c) asm volatile("mbarrier.init.shared.b64 [%0], %1;"::"r"(a),"r"(c):"memory")
#define MBAR_ARRIVE(a) asm volatile("mbarrier.arrive.shared.b64 _, [%0];"::"r"(a):"memory")
#define MBAR_EXPECT_TX(a,tx) asm volatile("mbarrier.arrive.expect_tx.shared.b64 _, [%0], %1;"::"r"(a),"r"(tx):"memory")
#define MBAR_WAIT(a,p) do{ uint32_t _m=(a),_p=(p),_d; \
    asm volatile("{\n\t.reg .pred q;\n\tmbarrier.try_wait.parity.acquire.cta.shared::cta.b64 q,[%1],%2;\n\tselp.b32 %0,1,0,q;\n\t}":"=r"(_d):"r"(_m),"r"(_p):"memory"); \
    if(!_d){ asm volatile("{\n\t.reg .pred q;\n\tW%=:\n\tmbarrier.try_wait.parity.acquire.cta.shared::cta.b64 q,[%0],%1,0x989680;\n\t@q bra.uni DN%=;\n\tbra.uni W%=;\n\tDN%=:\n\t}"::"r"(_m),"r"(_p):"memory"); } }while(0)
#define BULK_G2S(d,s,n,mb) asm volatile( \
    "cp.async.bulk.shared::cluster.global.mbarrier::complete_tx::bytes [%0], [%1], %2, [%3];" \
    :: "r"((uint32_t)(d)),"l"(s),"r"((uint32_t)(n)),"r"((uint32_t)(mb)) : "memory")

__device__ __forceinline__ void mma8(float* d, const uint32_t* a, const uint32_t* b){
    asm("mma.sync.aligned.m16n8k8.row.col.f32.tf32.tf32.f32 "
        "{%0,%1,%2,%3}, {%4,%5,%6,%7}, {%8,%9}, {%0,%1,%2,%3};"
        : "+f"(d[0]),"+f"(d[1]),"+f"(d[2]),"+f"(d[3])
        : "r"(a[0]),"r"(a[1]),"r"(a[2]),"r"(a[3]),"r"(b[0]),"r"(b[1]));
}
__device__ __forceinline__ float tf32r(float x){
    uint32_t b; asm("cvt.rna.tf32.f32 %0, %1;":"=r"(b):"f"(x)); return __uint_as_float(b);
}

// ---- prep: pack A so each (mb,dc) block of 16KB is contiguous ----
__global__ void packA(const float* __restrict__ src, float4* __restrict__ dst){
    int i = blockIdx.x*blockDim.x + threadIdx.x;
    int lane = i&31, ks = (i>>5)&3, tl = (i>>7)&7, dc = (i>>10)&7, mb = i>>13;
    int gr = lane>>2, gc = lane&3;
    int r0 = (mb*8+tl)*16 + gr, c0 = (dc*4+ks)*8 + gc;
    float4 v;
    v.x = tf32r(src[(size_t)r0*DD + c0]);
    v.y = tf32r(src[(size_t)(r0+8)*DD + c0]);
    v.z = tf32r(src[(size_t)r0*DD + c0+4]);
    v.w = tf32r(src[(size_t)(r0+8)*DD + c0+4]);
    dst[i] = v;
}
// ---- prep: pack B so each (nt,dc) block of 32KB is contiguous ----
__global__ void packB(const float* __restrict__ src, float2* __restrict__ dst){
    int i = blockIdx.x*blockDim.x + threadIdx.x;
    int lane = i&31, ks = (i>>5)&3, ntl = (i>>7)&31, dc = (i>>12)&7, nt = i>>15;
    int gr = lane>>2, gc = lane&3;
    int r = (nt*32+ntl)*8 + gr, c0 = (dc*4+ks)*8 + gc;
    float2 v;
    v.x = tf32r(src[(size_t)r*DD + c0]);
    v.y = tf32r(src[(size_t)r*DD + c0+4]);
    dst[i] = v;
}
__global__ void sumsq_kernel(const float* __restrict__ x, float* __restrict__ o, int rows){
    if(blockIdx.x==0 && threadIdx.x==0) g_cnt = 0;
    int row = blockIdx.x*(blockDim.x>>5) + (threadIdx.x>>5); if(row>=rows) return;
    int lane = threadIdx.x&31; const float* p = x + (size_t)row*DD; float s=0.f;
    #pragma unroll
    for(int c=lane;c<DD;c+=32){ float v=p[c]; s+=v*v; }
    #pragma unroll
    for(int ofs=16;ofs;ofs>>=1) s+=__shfl_down_sync(0xffffffffu,s,ofs);
    if(!lane) o[row]=s;
}

// ---- phase 1: 512-thread tf32 GEMM (warp tile 32x64) + min1/min2 + flagging ----
__global__ void __launch_bounds__(NTHR,1) vq_phase1(
    const float* __restrict__ E, const float* __restrict__ esq,
    float* __restrict__ outq, float* __restrict__ outi)
{
    extern __shared__ char smem[];
    const uint32_t sb = s2u(smem);
    const int tid = threadIdx.x, wid = tid>>5, lane = tid&31;
    const int r = lane>>2, c = lane&3;
    const int wm = wid&3, wn = wid>>2;     // 4 x 4 warp grid, warp tile 32x64
    const int m0 = blockIdx.x*BM, mb = blockIdx.x;

    const uint32_t fullb  = sb + BARS;
    const uint32_t emptyb = sb + BARS + 32;

    if(tid==0){
        #pragma unroll
        for(int s=0;s<4;s++){ MBAR_INIT(fullb+s*8,1); MBAR_INIT(emptyb+s*8,16); }
    }
    __syncthreads();
    if(tid==0){
        #pragma unroll
        for(int j=0;j<3;j++){
            MBAR_EXPECT_TX(fullb+j*8, STGB);
            const char* srcA = (const char*)g_xp + ((size_t)(mb*8 + (j&7)))*16384;
            const char* srcB = (const char*)g_ep + ((size_t)(j&7))*32768;
            BULK_G2S(sb + j*STGB,         srcA, 16384, fullb+j*8);
            BULK_G2S(sb + j*STGB + 16384, srcB, 32768, fullb+j*8);
        }
    }

    float m1[4], m2[4]; int i1[4];
    #pragma unroll
    for(int i=0;i<4;i++){ m1[i]=3.4e38f; m2[i]=3.4e38f; i1[i]=0; }

    for(int nt=0; nt<NNT; nt++){
        float acc[2][8][4];
        #pragma unroll
        for(int m=0;m<2;m++)
            #pragma unroll
            for(int n=0;n<8;n++){ acc[m][n][0]=0.f;acc[m][n][1]=0.f;acc[m][n][2]=0.f;acc[m][n][3]=0.f; }

        for(int dc=0; dc<8; dc++){
            const int it = nt*8 + dc;
            const int s = it&3;
            if(tid==0 && it+3 < NIT){
                const int j = it+3, sj = j&3;
                if(j>=4) MBAR_WAIT(emptyb+sj*8, ((j>>2)-1)&1);
                MBAR_EXPECT_TX(fullb+sj*8, STGB);
                const char* srcA = (const char*)g_xp + ((size_t)(mb*8 + (j&7)))*16384;
                const char* srcB = (const char*)g_ep + ((size_t)((j>>3)*8 + (j&7)))*32768;
                BULK_G2S(sb + sj*STGB,         srcA, 16384, fullb+sj*8);
                BULK_G2S(sb + sj*STGB + 16384, srcB, 32768, fullb+sj*8);
            }
            MBAR_WAIT(fullb+s*8, (it>>2)&1);
            const char* stp = smem + (size_t)s*STGB;

            #pragma unroll
            for(int ks=0; ks<4; ks++){
                float4 af[2]; float2 bf[8];
                #pragma unroll
                for(int m=0;m<2;m++)
                    af[m] = *(const float4*)(stp + ((wm*2+m)*4+ks)*512 + lane*16);
                #pragma unroll
                for(int n=0;n<8;n++)
                    bf[n] = *(const float2*)(stp + 16384 + ((wn*8+n)*4+ks)*256 + lane*8);
                #pragma unroll
                for(int m=0;m<2;m++)
                    #pragma unroll
                    for(int n=0;n<8;n++)
                        mma8(acc[m][n], (const uint32_t*)&af[m], (const uint32_t*)&bf[n]);
            }
            __syncwarp();
            if(lane==0) MBAR_ARRIVE(emptyb+s*8);
        }
        #pragma unroll
        for(int m=0;m<2;m++){
            const int rl=2*m, rh=2*m+1;
            #pragma unroll
            for(int n=0;n<8;n++){
                int colb = nt*BN + wn*64 + n*8 + 2*c;
                float e0 = __ldg(esq+colb), e1 = __ldg(esq+colb+1);
                float d;
                d = e0 - 2.f*acc[m][n][0];
                if(d<m1[rl]){m2[rl]=m1[rl];m1[rl]=d;i1[rl]=colb;} else if(d<m2[rl]) m2[rl]=d;
                d = e1 - 2.f*acc[m][n][1];
                if(d<m1[rl]){m2[rl]=m1[rl];m1[rl]=d;i1[rl]=colb+1;} else if(d<m2[rl]) m2[rl]=d;
                d = e0 - 2.f*acc[m][n][2];
                if(d<m1[rh]){m2[rh]=m1[rh];m1[rh]=d;i1[rh]=colb;} else if(d<m2[rh]) m2[rh]=d;
                d = e1 - 2.f*acc[m][n][3];
                if(d<m1[rh]){m2[rh]=m1[rh];m1[rh]=d;i1[rh]=colb+1;} else if(d<m2[rh]) m2[rh]=d;
            }
        }
    }

    // epilogue reduction overlays the (now dead) stage buffers
    float* s_m1 = (float*)(smem);
    float* s_m2 = (float*)(smem + 8192);
    int*   s_i1 = (int*)(smem + 16384);
    int*   s_idx= (int*)(smem + 24576);
    __syncthreads();
    #pragma unroll
    for(int i=0;i<4;i++){
        int row  = wm*32 + (i>>1)*16 + r + (i&1)*8;
        int slot = wn*4 + c;
        s_m1[row*16+slot] = m1[i];
        s_m2[row*16+slot] = m2[i];
        s_i1[row*16+slot] = i1[i];
    }
    __syncthreads();
    if(tid < 128){
        float bd = 3.4e38f; int bi = 0, tw = 0;
        #pragma unroll
        for(int t=0;t<16;t++){
            float d = s_m1[tid*16+t]; int ii = s_i1[tid*16+t];
            if(d<bd || (d==bd && ii<bi)){ bd=d; bi=ii; tw=t; }
        }
        float b2 = 3.4e38f;
        #pragma unroll
        for(int t=0;t<16;t++){
            float v = (t==tw) ? s_m2[tid*16+t] : s_m1[tid*16+t];
            b2 = fminf(b2, v);
        }
        s_idx[tid] = bi;
        outi[m0+tid] = (float)bi;
        if(b2 - bd < FLAG_T){
            g_best[m0+tid] = 0xFFFFFFFFFFFFFFFFull;
            int pos = atomicAdd(&g_cnt, 1);
            if(pos < FLAG_CAP) g_flag[pos] = m0 + tid;
        }
    }
    __syncthreads();
    for(int f=tid; f<BM*(DD/4); f+=NTHR){
        int rr = f>>6, c4 = f&63;
        float4 v = *(const float4*)(E + (size_t)s_idx[rr]*DD + c4*4);
        *(float4*)(outq + (size_t)(m0+rr)*DD + c4*4) = v;
    }
}

// ---- phase 2: exact fp32 rescore, K-split, atomicMin merge ----
__global__ void __launch_bounds__(128) vq_phase2(
    const float* __restrict__ X, const float* __restrict__ E, const float* __restrict__ esq)
{
    int cnt = g_cnt; if(cnt > FLAG_CAP) cnt = FLAG_CAP;
    const int rb = blockIdx.x;
    if(rb*P2M >= cnt) return;
    const int k0 = blockIdx.y * 128;
    __shared__ float Xs[16][P2M];
    __shared__ float Es[16][128];
    __shared__ int rows[P2M];
    __shared__ float s_bd[16][P2M];
    __shared__ int   s_bi[16][P2M];
    const int tid = threadIdx.x;
    const int tx = tid&15, ty = tid>>4;
    if(tid < P2M){
        int fi = rb*P2M + tid; if(fi >= cnt) fi = cnt-1;
        rows[tid] = g_flag[fi];
    }
    __syncthreads();

    float acc[8][8];
    #pragma unroll
    for(int i=0;i<8;i++)
        #pragma unroll
        for(int j=0;j<8;j++) acc[i][j]=0.f;

    for(int d0=0; d0<DD; d0+=16){
        #pragma unroll
        for(int l=0;l<2;l++){
            int f = tid + l*128, rr = f>>2, c4 = f&3;
            float4 v = *(const float4*)(X + (size_t)rows[rr]*DD + d0 + c4*4);
            Xs[c4*4+0][rr]=v.x; Xs[c4*4+1][rr]=v.y; Xs[c4*4+2][rr]=v.z; Xs[c4*4+3][rr]=v.w;
        }
        #pragma unroll
        for(int l=0;l<4;l++){
            int f = tid + l*128, rr = f>>2, c4 = f&3;
            float4 v = *(const float4*)(E + (size_t)(k0+rr)*DD + d0 + c4*4);
            Es[c4*4+0][rr]=v.x; Es[c4*4+1][rr]=v.y; Es[c4*4+2][rr]=v.z; Es[c4*4+3][rr]=v.w;
        }
        __syncthreads();
        #pragma unroll
        for(int kk=0;kk<16;kk++){
            float xr[8], er[8];
            #pragma unroll
            for(int i=0;i<8;i++) xr[i]=Xs[kk][ty*8+i];
            #pragma unroll
            for(int j=0;j<8;j++) er[j]=Es[kk][tx*8+j];
            #pragma unroll
            for(int i=0;i<8;i++)
                #pragma unroll
                for(int j=0;j<8;j++) acc[i][j]=fmaf(xr[i],er[j],acc[i][j]);
        }
        __syncthreads();
    }
    float bd[8]; int bi[8];
    #pragma unroll
    for(int i=0;i<8;i++){ bd[i]=3.4e38f; bi[i]=0; }
    #pragma unroll
    for(int i=0;i<8;i++)
        #pragma unroll
        for(int j=0;j<8;j++){
            int col = k0 + tx*8 + j;
            float d = __ldg(esq+col) - 2.f*acc[i][j];
            if(d < bd[i]){ bd[i]=d; bi[i]=col; }
        }
    #pragma unroll
    for(int i=0;i<8;i++){ s_bd[tx][ty*8+i]=bd[i]; s_bi[tx][ty*8+i]=bi[i]; }
    __syncthreads();
    if(tid < P2M){
        float b = s_bd[0][tid]; int ii = s_bi[0][tid];
        #pragma unroll
        for(int t=1;t<16;t++){
            float d = s_bd[t][tid]; int jj = s_bi[t][tid];
            if(d<b || (d==b && jj<ii)){ b=d; ii=jj; }
        }
        if(rb*P2M + tid < cnt){
            uint32_t u = __float_as_uint(b);
            u = (u & 0x80000000u) ? ~u : (u | 0x80000000u);
            unsigned long long key = ((unsigned long long)u << 32) | (unsigned)ii;
            atomicMin(&g_best[rows[tid]], key);
        }
    }
}

// ---- phase 3: write back flagged rows ----
__global__ void __launch_bounds__(256) vq_phase3(
    const float* __restrict__ E, float* __restrict__ outq, float* __restrict__ outi)
{
    int cnt = g_cnt; if(cnt > FLAG_CAP) cnt = FLAG_CAP;
    int i = blockIdx.x*8 + (threadIdx.x>>5);
    if(i >= cnt) return;
    int lane = threadIdx.x&31;
    int row = g_flag[i];
    int bi = (int)(g_best[row] & 0xFFFFFFFFull);
    if(lane==0) outi[row] = (float)bi;
    float4 v0 = *(const float4*)(E + (size_t)bi*DD + lane*8);
    float4 v1 = *(const float4*)(E + (size_t)bi*DD + lane*8 + 4);
    *(float4*)(outq + (size_t)row*DD + lane*8)     = v0;
    *(float4*)(outq + (size_t)row*DD + lane*8 + 4) = v1;
}

extern "C" void kernel_launch(void* const* d_in, const int* in_sizes, int n_in,
                              void* d_out, int out_size) {
    const float* X = (const float*)d_in[0];
    const float* E = (const float*)d_in[1];

    float4* xp; float2* ep; float* esq;
    cudaGetSymbolAddress((void**)&xp, g_xp);
    cudaGetSymbolAddress((void**)&ep, g_ep);
    cudaGetSymbolAddress((void**)&esq, g_esq);

    packA<<<NTOK*DD/4/256, 256>>>(X, xp);
    packB<<<KCB*DD/2/256, 256>>>(E, ep);
    sumsq_kernel<<<KCB/8, 256>>>(E, esq, KCB);   // also zeroes g_cnt

    float* outq = (float*)d_out;
    float* outi = (float*)d_out + (size_t)NTOK*DD;

    cudaFuncSetAttribute(vq_phase1, cudaFuncAttributeMaxDynamicSharedMemorySize, SMEMSZ);
    vq_phase1<<<NTOK/BM, NTHR, SMEMSZ>>>(E, esq, outq, outi);
    vq_phase2<<<dim3(FLAG_CAP/P2M, KCB/128), 128>>>(X, E, esq);
    vq_phase3<<<FLAG_CAP/8, 256>>>(E, outq, outi);
}